// round 11
// baseline (speedup 1.0000x reference)
#include <cuda_runtime.h>
#include <cuda_fp16.h>
#include <cstdint>

// ---------------- problem constants ----------------
#define N_TOK   262144
#define TOPK    2
#define NSLOTS  (N_TOK * TOPK)     // 524288
#define D       128
#define NEXP    8
#define TS      128                // slots per CTA-tile
#define MAXTILES (NSLOTS / TS + NEXP)   // 4104

// ---------------- device scratch ----------------
__device__ uint4 g_whp[NEXP * 2048];             // W fp16, packed [e][out 128][k 128] (32KB/expert)
__device__ int   g_seg[NEXP + 1];
__device__ int   g_tile_e[MAXTILES];
__device__ int   g_tile_s[MAXTILES];
__device__ int   g_ntiles;

// ---------------- helpers ----------------
__device__ __forceinline__ void mma_fp16(float* c, const uint32_t* a, uint32_t b0, uint32_t b1) {
    asm volatile("mma.sync.aligned.m16n8k16.row.col.f32.f16.f16.f32 "
        "{%0,%1,%2,%3}, {%4,%5,%6,%7}, {%8,%9}, {%0,%1,%2,%3};"
        : "+f"(c[0]), "+f"(c[1]), "+f"(c[2]), "+f"(c[3])
        : "r"(a[0]), "r"(a[1]), "r"(a[2]), "r"(a[3]), "r"(b0), "r"(b1));
}
#define RED_ADD_V2(ptr, a, b) \
    asm volatile("red.global.add.v2.f32 [%0], {%1, %2};" :: "l"(ptr), "f"(a), "f"(b) : "memory")
#define PREFETCH_L2(ptr) \
    asm volatile("prefetch.global.L2 [%0];" :: "l"(ptr))

__device__ __forceinline__ uint32_t f2h2(float lo, float hi) {
    __half2 h = __floats2half2_rn(lo, hi);
    return *reinterpret_cast<uint32_t*>(&h);
}

// convert 8 fp32 -> fp16 (16 B) — used by wconv
__device__ __forceinline__ uint4 cvt8h(const float* v) {
    uint32_t hu[4];
#pragma unroll
    for (int i = 0; i < 4; i++) {
        __half2 hp = __floats2half2_rn(v[2 * i], v[2 * i + 1]);
        hu[i] = *reinterpret_cast<uint32_t*>(&hp);
    }
    return make_uint4(hu[0], hu[1], hu[2], hu[3]);
}

// -------------------------------------------------------------------
// Prologue 1: weight fp32 [E, d_out, d_in] -> packed fp16 [e][out][k]
// -------------------------------------------------------------------
__global__ void wconv_kernel(const float* __restrict__ w) {
    int e = blockIdx.x;
    int tid = threadIdx.x;
    int row = tid >> 1;
    int half = tid & 1;
    const float* wr = w + ((size_t)e * D + row) * D;
    uint4* whe = g_whp + e * 2048;
#pragma unroll
    for (int g = 0; g < 8; g++) {
        int col0 = half * 64 + g * 8;
        float v[8];
#pragma unroll
        for (int i = 0; i < 8; i++) v[i] = wr[col0 + i];
        whe[row * 16 + half * 8 + g] = cvt8h(v);
    }
}

// -------------------------------------------------------------------
// Prologue 2: expert segments + dense tile map
// -------------------------------------------------------------------
__global__ void seg_kernel(const int* __restrict__ sei) {
    __shared__ int seg[NEXP + 1];
    __shared__ int cnts[NEXP];
    int t = threadIdx.x;
    if (t <= NEXP) {
        int lo = 0, hi = NSLOTS;
        while (lo < hi) {
            int mid = (lo + hi) >> 1;
            if (sei[mid] < t) lo = mid + 1; else hi = mid;
        }
        seg[t] = lo;
        g_seg[t] = lo;
    }
    __syncthreads();
    if (t < NEXP) cnts[t] = (seg[t + 1] - seg[t] + TS - 1) / TS;
    __syncthreads();
    if (t < NEXP) {
        int off = 0;
        for (int i = 0; i < t; i++) off += cnts[i];
        int s = seg[t];
        for (int i = 0; i < cnts[t]; i++) {
            g_tile_e[off + i] = t;
            g_tile_s[off + i] = s + i * TS;
        }
    }
    if (t == 0) {
        int tot = 0;
        for (int i = 0; i < NEXP; i++) tot += cnts[i];
        g_ntiles = tot;
    }
}

// -------------------------------------------------------------------
// Prologue 3: zero-init out (atomic accumulation target)
// -------------------------------------------------------------------
__global__ void zero_kernel(float4* __restrict__ out) {
    size_t idx = (size_t)blockIdx.x * blockDim.x + threadIdx.x;
    out[idx] = make_float4(0.f, 0.f, 0.f, 0.f);
}

// -------------------------------------------------------------------
// Main: barrier-free warp-streaming fp16 HMMA, A+B via LDG, no smem
// -------------------------------------------------------------------
extern "C" __global__ void __launch_bounds__(256, 2)
moe_mma_kernel(const float* __restrict__ x,
               const float* __restrict__ gates,
               const int*   __restrict__ ssi,
               float* __restrict__ out) {
    int ntiles = g_ntiles;
    int nc = gridDim.x;
    int per = ntiles / nc, rem = ntiles % nc;
    int t0 = blockIdx.x * per + min((int)blockIdx.x, rem);
    int t1 = t0 + per + (blockIdx.x < rem ? 1 : 0);
    if (t0 >= t1) return;

    int tid = threadIdx.x;
    int wid = tid >> 5;
    int lane = tid & 31;

    // warp tile: wr 0..3 (32 slots), wc 0..1 (64 outs)
    int wr = wid & 3;
    int wc = wid >> 2;
    int row_lo = lane >> 2;           // 0..7 : fragment row within m8 / B col within n8
    int c0 = (lane & 3) * 2;          // k-pair base within k16 chunk

    // B pointer: W[e][out][k] fp16; thread's B col (out) per ng = wc*64 + ng*8 + row_lo
    const char* wbase_all = (const char*)g_whp;

    for (int t = t0; t < t1; t++) {
        int e  = g_tile_e[t];
        int s0 = g_tile_s[t];
        int cnt = min(TS, g_seg[e + 1] - s0);

        // ---- per-thread metadata: 4 slot rows (mt in {0,1} x h in {0,1}) ----
        int   jrow[4];
        int   f[4];
        float gv[4];
        const float* xr[4];
#pragma unroll
        for (int i = 0; i < 4; i++) {
            int mt = i >> 1, h = i & 1;
            int j = wr * 32 + mt * 16 + h * 8 + row_lo;
            jrow[i] = j;
            bool ok = j < cnt;
            int fi = ok ? ssi[s0 + j] : 0;
            f[i]  = fi;
            gv[i] = ok ? gates[fi] : 0.f;
            xr[i] = x + (size_t)(fi >> 1) * D;
        }

        // ---- L2-prefetch next tile's X rows (1 lane per row) ----
        if (t + 1 < t1 && (lane & 3) == 0 && wc == 0) {
            int en  = g_tile_e[t + 1];
            int s0n = g_tile_s[t + 1];
            int cntn = min(TS, g_seg[en + 1] - s0n);
#pragma unroll
            for (int i = 0; i < 4; i++) {
                int mt = i >> 1, h = i & 1;
                int j = wr * 32 + mt * 16 + h * 8 + row_lo;
                if (j < cntn) {
                    const char* pf = (const char*)x + (size_t)(ssi[s0n + j] >> 1) * 512;
                    PREFETCH_L2(pf);
                    PREFETCH_L2(pf + 128);
                    PREFETCH_L2(pf + 256);
                    PREFETCH_L2(pf + 384);
                }
            }
        }

        const char* wp = wbase_all + (size_t)e * 32768
                         + (wc * 64 + row_lo) * 256 + c0 * 2;

        // ---- MMA mainloop: A + B straight from GMEM ----
        float acc[2][8][4];
#pragma unroll
        for (int mt = 0; mt < 2; mt++)
#pragma unroll
            for (int nt = 0; nt < 8; nt++)
#pragma unroll
                for (int i = 0; i < 4; i++) acc[mt][nt][i] = 0.f;

#pragma unroll
        for (int kk = 0; kk < 8; kk++) {
            int kc = kk * 16 + c0;
            // A fragments: 8 LDG.64 (fp32 pairs) -> cvt to half2
            float2 alo[4], ahi[4];
#pragma unroll
            for (int i = 0; i < 4; i++) {
                alo[i] = *(const float2*)(xr[i] + kc);
                ahi[i] = *(const float2*)(xr[i] + kc + 8);
            }
            // B fragments: 16 LDG.32 (fp16x2), L1-hot
            uint32_t b0[8], b1[8];
#pragma unroll
            for (int ng = 0; ng < 8; ng++) {
                const char* wq = wp + ng * 2048 + kk * 32;
                b0[ng] = *(const uint32_t*)(wq);
                b1[ng] = *(const uint32_t*)(wq + 16);
            }
            uint32_t a[2][4];
#pragma unroll
            for (int mt = 0; mt < 2; mt++) {
                a[mt][0] = f2h2(alo[mt * 2].x,     alo[mt * 2].y);
                a[mt][1] = f2h2(alo[mt * 2 + 1].x, alo[mt * 2 + 1].y);
                a[mt][2] = f2h2(ahi[mt * 2].x,     ahi[mt * 2].y);
                a[mt][3] = f2h2(ahi[mt * 2 + 1].x, ahi[mt * 2 + 1].y);
            }
#pragma unroll
            for (int ng = 0; ng < 8; ng++) {
#pragma unroll
                for (int mt = 0; mt < 2; mt++)
                    mma_fp16(acc[mt][ng], a[mt], b0[ng], b1[ng]);
            }
        }

        // ---- fused epilogue: gate + atomic-add (exactly 2 adds/elem) ----
        {
            int colb = wc * 64 + c0;
#pragma unroll
            for (int mt = 0; mt < 2; mt++) {
                int ia = mt * 2, ib = mt * 2 + 1;
                bool oka = jrow[ia] < cnt, okb = jrow[ib] < cnt;
                float ga = gv[ia], gb = gv[ib];
                float* da = out + (size_t)(f[ia] >> 1) * D + colb;
                float* db = out + (size_t)(f[ib] >> 1) * D + colb;
#pragma unroll
                for (int ng = 0; ng < 8; ng++) {
                    if (oka)
                        RED_ADD_V2(da + ng * 8, acc[mt][ng][0] * ga, acc[mt][ng][1] * ga);
                    if (okb)
                        RED_ADD_V2(db + ng * 8, acc[mt][ng][2] * gb, acc[mt][ng][3] * gb);
                }
            }
        }
    }
}

// -------------------------------------------------------------------
extern "C" void kernel_launch(void* const* d_in, const int* in_sizes, int n_in,
                              void* d_out, int out_size) {
    const float* inputs = (const float*)d_in[0];
    const float* weight = (const float*)d_in[1];
    const float* gates  = (const float*)d_in[2];
    const int*   sei    = (const int*)d_in[4];
    const int*   ssi    = (const int*)d_in[5];
    float* out = (float*)d_out;

    int nsm = 148;
    cudaDeviceGetAttribute(&nsm, cudaDevAttrMultiProcessorCount, 0);

    wconv_kernel<<<NEXP, 256>>>(weight);
    seg_kernel<<<1, 32>>>(sei);
    zero_kernel<<<(N_TOK * D / 4) / 256, 256>>>((float4*)out);

    moe_mma_kernel<<<2 * nsm, 256>>>(inputs, gates, ssi, out);
}

// round 12
// speedup vs baseline: 1.1522x; 1.1522x over previous
#include <cuda_runtime.h>
#include <cuda_fp16.h>
#include <cstdint>

// ---------------- problem constants ----------------
#define N_TOK   262144
#define TOPK    2
#define NSLOTS  (N_TOK * TOPK)     // 524288
#define D       128
#define NEXP    8
#define TS      128                // slots per tile
#define MAXTILES (NSLOTS / TS + NEXP)   // 4104

// ---------------- device scratch ----------------
__device__ float g_yscat[(size_t)NSLOTS * D];    // gated per-slot outputs (256 MiB)
__device__ uint4 g_whp[NEXP * 2048];             // W fp16, packed [e][out][k] (32KB/expert)
__device__ int   g_seg[NEXP + 1];
__device__ int   g_tile_e[MAXTILES];
__device__ int   g_tile_s[MAXTILES];
__device__ int   g_ntiles;

// ---------------- helpers ----------------
__device__ __forceinline__ uint32_t smem_u32(const void* p) {
    uint32_t a;
    asm("{ .reg .u64 t; cvta.to.shared.u64 t, %1; cvt.u32.u64 %0, t; }" : "=r"(a) : "l"(p));
    return a;
}
__device__ __forceinline__ void ldsm_x4(uint32_t* r, uint32_t addr) {
    asm volatile("ldmatrix.sync.aligned.m8n8.x4.shared.b16 {%0,%1,%2,%3}, [%4];"
        : "=r"(r[0]), "=r"(r[1]), "=r"(r[2]), "=r"(r[3]) : "r"(addr));
}
__device__ __forceinline__ void mma_fp16(float* c, const uint32_t* a, uint32_t b0, uint32_t b1) {
    asm volatile("mma.sync.aligned.m16n8k16.row.col.f32.f16.f16.f32 "
        "{%0,%1,%2,%3}, {%4,%5,%6,%7}, {%8,%9}, {%0,%1,%2,%3};"
        : "+f"(c[0]), "+f"(c[1]), "+f"(c[2]), "+f"(c[3])
        : "r"(a[0]), "r"(a[1]), "r"(a[2]), "r"(a[3]), "r"(b0), "r"(b1));
}

// convert 8 fp32 -> fp16 (16 B)
__device__ __forceinline__ uint4 cvt8h(const float* v) {
    uint32_t hu[4];
#pragma unroll
    for (int i = 0; i < 4; i++) {
        __half2 hp = __floats2half2_rn(v[2 * i], v[2 * i + 1]);
        hu[i] = *reinterpret_cast<uint32_t*>(&hp);
    }
    return make_uint4(hu[0], hu[1], hu[2], hu[3]);
}

// -------------------------------------------------------------------
// Prologue 1: weight fp32 [E, d_out, d_in] -> packed fp16
// -------------------------------------------------------------------
__global__ void wconv_kernel(const float* __restrict__ w) {
    int e = blockIdx.x;
    int tid = threadIdx.x;
    int row = tid >> 1;
    int half = tid & 1;
    const float* wr = w + ((size_t)e * D + row) * D;
    uint4* whe = g_whp + e * 2048;
#pragma unroll
    for (int g = 0; g < 8; g++) {
        int col0 = half * 64 + g * 8;
        float v[8];
#pragma unroll
        for (int i = 0; i < 8; i++) v[i] = wr[col0 + i];
        whe[row * 16 + half * 8 + g] = cvt8h(v);
    }
}

// -------------------------------------------------------------------
// Prologue 2: expert segments + dense tile map
// -------------------------------------------------------------------
__global__ void seg_kernel(const int* __restrict__ sei) {
    __shared__ int seg[NEXP + 1];
    __shared__ int cnts[NEXP];
    int t = threadIdx.x;
    if (t <= NEXP) {
        int lo = 0, hi = NSLOTS;
        while (lo < hi) {
            int mid = (lo + hi) >> 1;
            if (sei[mid] < t) lo = mid + 1; else hi = mid;
        }
        seg[t] = lo;
        g_seg[t] = lo;
    }
    __syncthreads();
    if (t < NEXP) cnts[t] = (seg[t + 1] - seg[t] + TS - 1) / TS;
    __syncthreads();
    if (t < NEXP) {
        int off = 0;
        for (int i = 0; i < t; i++) off += cnts[i];
        int s = seg[t];
        for (int i = 0; i < cnts[t]; i++) {
            g_tile_e[off + i] = t;
            g_tile_s[off + i] = s + i * TS;
        }
    }
    if (t == 0) {
        int tot = 0;
        for (int i = 0; i < NEXP; i++) tot += cnts[i];
        g_ntiles = tot;
    }
}

// -------------------------------------------------------------------
// SMEM layout (69 KB -> 2 CTAs/SM)
// -------------------------------------------------------------------
#define XROWB 272
#define IMGB  (128 * XROWB)          // 34816
#define OFF_SHF 0
#define OFF_SHG 512
#define OFF_XH  1024
#define OFF_WH  (OFF_XH + IMGB)      // 35840
#define SMEM_TOTAL (OFF_WH + IMGB)   // 70656

// -------------------------------------------------------------------
// Main: persistent fp16 HMMA, 2 CTAs/SM, LDG gather + STG scatter
// -------------------------------------------------------------------
extern "C" __global__ void __launch_bounds__(256, 2)
moe_mma_kernel(const float* __restrict__ x,
               const float* __restrict__ gates,
               const int*   __restrict__ ssi) {
    int ntiles = g_ntiles;
    int nc = gridDim.x;
    int per = ntiles / nc, rem = ntiles % nc;
    int t0 = blockIdx.x * per + min((int)blockIdx.x, rem);
    int t1 = t0 + per + (blockIdx.x < rem ? 1 : 0);
    if (t0 >= t1) return;

    extern __shared__ char smem[];
    uint32_t sb = smem_u32(smem);
    int*   sh_f = (int*)(smem + OFF_SHF);
    float* sh_g = (float*)(smem + OFF_SHG);

    int tid = threadIdx.x;
    int wid = tid >> 5;
    int lane = tid & 31;
    int r = tid >> 1;                 // staging row (2 threads per row)
    int half = tid & 1;

    // warp tiles: wr 0..3 (32 slots), wc 0..1 (64 outs)
    int wr = wid & 3;
    int wc = wid >> 2;
    int lrow = (lane & 7) | (lane & 8);
    int kby  = (lane >> 4) * 16;
    uint32_t aA = sb + OFF_XH + (uint32_t)(wr * 32 + lrow) * XROWB + kby;
    uint32_t aB = sb + OFF_WH + (uint32_t)(wc * 64 + lrow) * XROWB + kby;

    // ---- prime tile t0 metadata ----
    int e  = g_tile_e[t0];
    int s0 = g_tile_s[t0];
    int cnt = min(TS, g_seg[e + 1] - s0);
    int   fcur = (r < cnt) ? ssi[s0 + r] : 0;
    float gcur = (r < cnt) ? gates[fcur] : 0.f;

    int staged_e = -1;

    for (int t = t0; t < t1; t++) {
        // ---- issue X gather for this tile (first half of each 32B chunk) ----
        float4 xr[8];
        const float4* xp = (const float4*)x + (size_t)(fcur >> 1) * 32 + half * 16;
#pragma unroll
        for (int g = 0; g < 8; g++) xr[g] = xp[g * 2];

        // ---- prefetch metadata for t+1 ----
        bool havenext = (t + 1 < t1);
        int en = e, s0n = s0, cntn = cnt, fnxt = 0; float gnxt = 0.f;
        if (havenext) {
            en  = g_tile_e[t + 1];
            s0n = g_tile_s[t + 1];
            cntn = min(TS, g_seg[en + 1] - s0n);
            fnxt = (r < cntn) ? ssi[s0n + r] : 0;
            gnxt = (r < cntn) ? gates[fnxt] : 0.f;
        }

        __syncthreads();       // prev tile MMA done -> safe to overwrite image

        // ---- stage W on expert change (rare) ----
        if (e != staged_e) {
            const uint4* whe = g_whp + e * 2048;
#pragma unroll
            for (int i = 0; i < 8; i++) {
                int cid = tid + 256 * i;
                int row = cid >> 4;
                int w16 = cid & 15;
                *(uint4*)(smem + OFF_WH + row * XROWB + w16 * 16) = whe[cid];
            }
            staged_e = e;
        }

        // ---- metadata to smem ----
        if (!half) {
            sh_f[r] = fcur;
            sh_g[r] = gcur;
        }

        // ---- convert + STS fp16 image ----
        {
            char* xh = smem + OFF_XH;
#pragma unroll
            for (int g = 0; g < 8; g++) {
                float4 a = xr[g];
                float4 b = xp[g * 2 + 1];      // same 32B sector -> L1 hit
                float v[8] = {a.x, a.y, a.z, a.w, b.x, b.y, b.z, b.w};
                uint4 hv = cvt8h(v);
                *(uint4*)(xh + (uint32_t)r * XROWB + (half * 64 + g * 8) * 2) = hv;
            }
        }
        __syncthreads();       // image + meta ready

        // ---- MMA: single fp16 pass ----
        float acc[2][8][4];
#pragma unroll
        for (int mt = 0; mt < 2; mt++)
#pragma unroll
            for (int nt = 0; nt < 8; nt++)
#pragma unroll
                for (int i = 0; i < 4; i++) acc[mt][nt][i] = 0.f;

#pragma unroll
        for (int kk = 0; kk < 8; kk++) {
            uint32_t kb = kk * 32;
            uint32_t ah[2][4];
            ldsm_x4(ah[0], aA + kb);
            ldsm_x4(ah[1], aA + 16 * XROWB + kb);
#pragma unroll
            for (int ng = 0; ng < 4; ng++) {
                uint32_t bh[4];
                ldsm_x4(bh, aB + ng * 16 * XROWB + kb);
#pragma unroll
                for (int mt = 0; mt < 2; mt++) {
                    mma_fp16(acc[mt][2 * ng],     ah[mt], bh[0], bh[2]);
                    mma_fp16(acc[mt][2 * ng + 1], ah[mt], bh[1], bh[3]);
                }
            }
        }

        // ---- epilogue: gate + STG scatter into slot buffer (no atomics) ----
        {
            int row_lo = lane >> 2;
            int col0 = wc * 64 + (lane & 3) * 2;
#pragma unroll
            for (int mt = 0; mt < 2; mt++) {
                int ja = wr * 32 + mt * 16 + row_lo;
                int jb = ja + 8;
                bool oka = ja < cnt, okb = jb < cnt;
                float ga = sh_g[ja], gb = sh_g[jb];
                float* da = g_yscat + (size_t)sh_f[ja] * D + col0;
                float* db = g_yscat + (size_t)sh_f[jb] * D + col0;
#pragma unroll
                for (int nt = 0; nt < 8; nt++) {
                    if (oka) {
                        float2 v = make_float2(acc[mt][nt][0] * ga, acc[mt][nt][1] * ga);
                        *(float2*)(da + nt * 8) = v;
                    }
                    if (okb) {
                        float2 v = make_float2(acc[mt][nt][2] * gb, acc[mt][nt][3] * gb);
                        *(float2*)(db + nt * 8) = v;
                    }
                }
            }
        }

        // rotate tile state
        e = en; s0 = s0n; cnt = cntn; fcur = fnxt; gcur = gnxt;
    }
}

// -------------------------------------------------------------------
// combine: out[n] = y[2n] + y[2n+1]  (measured at 84% DRAM roofline)
// -------------------------------------------------------------------
__global__ void combine_kernel(float* __restrict__ out) {
    size_t idx = (size_t)blockIdx.x * blockDim.x + threadIdx.x;
    const float4* y4 = (const float4*)g_yscat;
    size_t n = idx >> 5;
    int d4 = (int)(idx & 31);
    float4 a = y4[n * 64 + d4];
    float4 b = y4[n * 64 + 32 + d4];
    ((float4*)out)[idx] = make_float4(a.x + b.x, a.y + b.y, a.z + b.z, a.w + b.w);
}

// -------------------------------------------------------------------
extern "C" void kernel_launch(void* const* d_in, const int* in_sizes, int n_in,
                              void* d_out, int out_size) {
    const float* inputs = (const float*)d_in[0];
    const float* weight = (const float*)d_in[1];
    const float* gates  = (const float*)d_in[2];
    const int*   sei    = (const int*)d_in[4];
    const int*   ssi    = (const int*)d_in[5];
    float* out = (float*)d_out;

    int nsm = 148;
    cudaDeviceGetAttribute(&nsm, cudaDevAttrMultiProcessorCount, 0);

    cudaFuncSetAttribute(moe_mma_kernel,
                         cudaFuncAttributeMaxDynamicSharedMemorySize, SMEM_TOTAL);

    wconv_kernel<<<NEXP, 256>>>(weight);
    seg_kernel<<<1, 32>>>(sei);

    moe_mma_kernel<<<2 * nsm, 256, SMEM_TOTAL>>>(inputs, gates, ssi);

    combine_kernel<<<(N_TOK * D / 4) / 256, 256>>>(out);
}